// round 3
// baseline (speedup 1.0000x reference)
#include <cuda_runtime.h>

#define WIDTH 4096
#define DEPTH 32
typedef unsigned long long ull;

// stage-ordered (cos,sin) table: [(t*8 + k)*256 + tid]
__device__ float2 g_theta[32 * 8 * 256];

static __device__ __forceinline__ ull pack2(float lo, float hi) {
    ull r; asm("mov.b64 %0, {%1,%2};" : "=l"(r) : "f"(lo), "f"(hi)); return r;
}
static __device__ __forceinline__ void unpack2(ull v, float &lo, float &hi) {
    asm("mov.b64 {%0,%1}, %2;" : "=f"(lo), "=f"(hi) : "l"(v));
}
static __device__ __forceinline__ ull mul2(ull a, ull b) {
    ull r; asm("mul.rn.f32x2 %0, %1, %2;" : "=l"(r) : "l"(a), "l"(b)); return r;
}
static __device__ __forceinline__ ull fma2(ull a, ull b, ull c) {
    ull r; asm("fma.rn.f32x2 %0, %1, %2, %3;" : "=l"(r) : "l"(a), "l"(b), "l"(c)); return r;
}

// logical column index u from (pattern, register slot cr, thread id)
// pat 0: u[11:8]=cr, u[7:0]=tid
// pat 1: u[11:8]=tid[7:4], u[7:4]=cr, u[3:0]=tid[3:0]
// pat 2: u[11:8]=tid[7:4], u[7:4]=tid[3:0], u[3:0]=cr
static __device__ __forceinline__ int asmU_rt(int pat, int cr, int tid) {
    if (pat == 0) return (cr << 8) | tid;
    if (pat == 1) return (cr << 4) | (tid & 15) | ((tid & 0xF0) << 4);
    return cr | ((tid & 15) << 4) | ((tid & 0xF0) << 4);
}
template<int PAT> static __device__ __forceinline__ int asmU(int cr, int tid) {
    return asmU_rt(PAT, cr, tid);
}
// swizzle over 16B smem words; keeps bank-slot bits injective in all patterns
static __device__ __forceinline__ int swz(int u) {
    return u ^ (((u >> 4) ^ (u >> 8)) & 15);
}

__global__ void bfly_theta_kernel(const float* __restrict__ params) {
    int idx = blockIdx.x * blockDim.x + threadIdx.x;  // 65536
    int t = idx >> 11, k = (idx >> 8) & 7, tid = idx & 255;
    int pat = (t >> 2) % 3;
    int m = 3 - (t & 3);                              // register bit for stage
    int i0 = ((k >> m) << (m + 1)) | (k & ((1 << m) - 1)); // pair slot, bit m = 0
    int u = asmU_rt(pat, i0, tid);
    int s = t % 12;
    int ur = s ? (((u << s) | (u >> (12 - s))) & 4095) : u; // rotl12(u, t)
    float th = params[(ur & 2047) * DEPTH + t];
    float c, sn;
    sincosf(th, &sn, &c);
    g_theta[idx] = make_float2(c, sn);
}

template<int M>
static __device__ __forceinline__ void stage(ull d[32], int t, int tid) {
    const float2* th = g_theta + (t << 11) + tid;
#pragma unroll
    for (int k = 0; k < 8; k++) {
        float2 cs = th[k << 8];
        ull cc = pack2(cs.x, cs.x);
        ull ss = pack2(cs.y, cs.y);
        ull ns = ss ^ 0x8000000080000000ULL;  // (-s,-s)
        int i0 = ((k >> M) << (M + 1)) | (k & ((1 << M) - 1));
        int i1 = i0 | (1 << M);
#pragma unroll
        for (int rp = 0; rp < 2; rp++) {
            ull x0 = d[2 * i0 + rp], x1 = d[2 * i1 + rp];
            d[2 * i0 + rp] = fma2(x0, cc, mul2(x1, ss));  // y0 =  c*x0 + s*x1
            d[2 * i1 + rp] = fma2(x0, ns, mul2(x1, cc));  // y1 = -s*x0 + c*x1
        }
    }
}

static __device__ __forceinline__ void phase4(ull d[32], int t0, int tid) {
    stage<3>(d, t0, tid);
    stage<2>(d, t0 + 1, tid);
    stage<1>(d, t0 + 2, tid);
    stage<0>(d, t0 + 3, tid);
}

template<int PO, int PN>
static __device__ __forceinline__ void xpose(ull d[32], int tid, longlong2* sm) {
#pragma unroll
    for (int cr = 0; cr < 16; cr++)
        sm[swz(asmU<PO>(cr, tid))] =
            make_longlong2((long long)d[2 * cr], (long long)d[2 * cr + 1]);
    __syncthreads();
#pragma unroll
    for (int cr = 0; cr < 16; cr++) {
        longlong2 v = sm[swz(asmU<PN>(cr, tid))];
        d[2 * cr] = (ull)v.x;
        d[2 * cr + 1] = (ull)v.y;
    }
    __syncthreads();
}

__global__ __launch_bounds__(256, 2)
void bfly_main_kernel(const float* __restrict__ X, float* __restrict__ out) {
    extern __shared__ longlong2 sm[];  // 4096 x 16B = 64KB
    int tid = threadIdx.x;
    size_t row0 = (size_t)blockIdx.x * 4;
    const float* x = X + row0 * WIDTH;
    float* o = out + row0 * WIDTH;

    ull d[32];  // [cr*2+rp]: rp0 = rows(0,1) packed, rp1 = rows(2,3) packed
#pragma unroll
    for (int cr = 0; cr < 16; cr++) {   // pattern-0 load, coalesced
        int u = (cr << 8) | tid;
        d[2 * cr]     = pack2(x[u],             x[WIDTH + u]);
        d[2 * cr + 1] = pack2(x[2 * WIDTH + u], x[3 * WIDTH + u]);
    }

    phase4(d, 0, tid);  xpose<0, 1>(d, tid, sm);
    phase4(d, 4, tid);  xpose<1, 2>(d, tid, sm);
    phase4(d, 8, tid);  xpose<2, 0>(d, tid, sm);
    phase4(d, 12, tid); xpose<0, 1>(d, tid, sm);
    phase4(d, 16, tid); xpose<1, 2>(d, tid, sm);
    phase4(d, 20, tid); xpose<2, 0>(d, tid, sm);
    phase4(d, 24, tid); xpose<0, 1>(d, tid, sm);
    phase4(d, 28, tid);

    // regs now in pattern 1; park in smem by logical u, then read so the
    // rotated output index o = rotl12(u,8) is coalesced: for o=(cr<<8)|tid,
    // u = rotl12(o,4) = (tid<<4)|cr  (conflict-free under swz).
#pragma unroll
    for (int cr = 0; cr < 16; cr++)
        sm[swz(asmU<1>(cr, tid))] =
            make_longlong2((long long)d[2 * cr], (long long)d[2 * cr + 1]);
    __syncthreads();
#pragma unroll
    for (int cr = 0; cr < 16; cr++) {
        int oc = (cr << 8) | tid;                      // output column
        int u = ((oc << 4) | (oc >> 8)) & 4095;        // rotl12(oc, 4)
        longlong2 v = sm[swz(u)];
        float a, b;
        unpack2((ull)v.x, a, b);
        o[oc] = a;
        o[WIDTH + oc] = b;
        unpack2((ull)v.y, a, b);
        o[2 * WIDTH + oc] = a;
        o[3 * WIDTH + oc] = b;
    }
}

extern "C" void kernel_launch(void* const* d_in, const int* in_sizes, int n_in,
                              void* d_out, int out_size) {
    const float* X = (const float*)d_in[0];
    const float* params = (const float*)d_in[1];
    if (n_in >= 2 && in_sizes[0] == 2048 * 32) {  // guard against input-order swap
        X = (const float*)d_in[1];
        params = (const float*)d_in[0];
    }
    cudaFuncSetAttribute(bfly_main_kernel,
                         cudaFuncAttributeMaxDynamicSharedMemorySize, 65536);
    bfly_theta_kernel<<<256, 256>>>(params);
    bfly_main_kernel<<<4096, 256, 65536>>>(X, (float*)d_out);
}